// round 14
// baseline (speedup 1.0000x reference)
#include <cuda_runtime.h>
#include <cstdint>

#define NN 8192
#define DD 256
#define KK 32
#define CAND 48
#define CMPCAP 1408

typedef unsigned long long u64;

// ---- scratch (no cudaMalloc allowed) ----
__device__ float g_S[(size_t)NN * (size_t)NN];   // 256 MB sim matrix
__device__ float g_An[(size_t)NN * DD];          // fp32-normalized A (ref rounding)
__device__ float g_Bn[(size_t)NN * DD];          // fp32-normalized B
__device__ float g_ria[NN];                      // fl(1/na) -- normalized one-hot element
__device__ float g_rib[NN];

// ===== packed dual-fp32 FMA =====
__device__ __forceinline__ u64 pack2(float lo, float hi) {
    u64 r; asm("mov.b64 %0, {%1, %2};" : "=l"(r) : "f"(lo), "f"(hi)); return r;
}
__device__ __forceinline__ void unpack2(u64 v, float& lo, float& hi) {
    asm("mov.b64 {%0, %1}, %2;" : "=f"(lo), "=f"(hi) : "l"(v));
}
__device__ __forceinline__ u64 ffma2(u64 a, u64 b, u64 c) {
    u64 d; asm("fma.rn.f32x2 %0, %1, %2, %3;" : "=l"(d) : "l"(a), "l"(b), "l"(c)); return d;
}

// ===== Eigen pexp, range-specialized for x in [-2.3, 0] =====
// Verified bit-identical (R11/R12): clamp, lo-branch and final fmax are
// identities on this domain; single power-of-2 scale suffices.
__device__ __forceinline__ float pexp_eigen(float x) {
    const float cst_LOG2EF = 1.44269504088896341f;
    const float p0 = 1.9875691500E-4f, p1 = 1.3981999507E-3f, p2 = 8.3334519073E-3f;
    const float p3 = 4.1665795894E-2f, p4 = 1.6666665459E-1f, p5 = 5.0000001201E-1f;
    float m = floorf(__fmaf_rn(x, cst_LOG2EF, 0.5f));
    const float cst_nln2 = -0.6931471805599453f;
    float r  = __fmaf_rn(m, cst_nln2, x);
    float r2 = __fmul_rn(r, r);
    float r3 = __fmul_rn(r2, r);
    float y  = __fmaf_rn(p0, r, p1);
    float y1 = __fmaf_rn(p3, r, p4);
    float y2 = __fadd_rn(r, 1.0f);
    y  = __fmaf_rn(y, r, p2);
    y1 = __fmaf_rn(y1, r, p5);
    y  = __fmaf_rn(y, r3, y1);
    y  = __fmaf_rn(y, r2, y2);
    float f1 = __uint_as_float((unsigned)(127 + (int)m) << 23);
    return __fmul_rn(y, f1);
}

// =========== K0: fp32 normalization like the reference (UNCHANGED bits) ===========
__global__ __launch_bounds__(256) void normalize_kernel(const float* __restrict__ A,
                                                        const float* __restrict__ B) {
    int warp = threadIdx.x >> 5, lane = threadIdx.x & 31;
    int row = blockIdx.x * 8 + warp;
    if (row >= NN) return;

    {
        const float4* ar = (const float4*)(A + (size_t)row * DD);
        float4 v0 = ar[lane], v1 = ar[lane + 32];
        double s = (double)v0.x * v0.x + (double)v0.y * v0.y +
                   (double)v0.z * v0.z + (double)v0.w * v0.w +
                   (double)v1.x * v1.x + (double)v1.y * v1.y +
                   (double)v1.z * v1.z + (double)v1.w * v1.w;
#pragma unroll
        for (int o = 16; o; o >>= 1) s += __shfl_xor_sync(0xffffffffu, s, o);
        float na = __fsqrt_rn((float)(s + 1.0));
        float4* dst = (float4*)(g_An + (size_t)row * DD);
        float4 w0, w1;
        w0.x = __fdiv_rn(v0.x, na); w0.y = __fdiv_rn(v0.y, na);
        w0.z = __fdiv_rn(v0.z, na); w0.w = __fdiv_rn(v0.w, na);
        w1.x = __fdiv_rn(v1.x, na); w1.y = __fdiv_rn(v1.y, na);
        w1.z = __fdiv_rn(v1.z, na); w1.w = __fdiv_rn(v1.w, na);
        dst[lane] = w0; dst[lane + 32] = w1;
        if (lane == 0) g_ria[row] = __fdiv_rn(1.0f, na);
    }
    {
        const float4* br = (const float4*)(B + (size_t)row * DD);
        float4 v0 = br[lane], v1 = br[lane + 32];
        double s = (double)v0.x * v0.x + (double)v0.y * v0.y +
                   (double)v0.z * v0.z + (double)v0.w * v0.w +
                   (double)v1.x * v1.x + (double)v1.y * v1.y +
                   (double)v1.z * v1.z + (double)v1.w * v1.w;
#pragma unroll
        for (int o = 16; o; o >>= 1) s += __shfl_xor_sync(0xffffffffu, s, o);
        float nb = __fsqrt_rn((float)(s + 1.0));
        float4* dst = (float4*)(g_Bn + (size_t)row * DD);
        float4 w0, w1;
        w0.x = __fdiv_rn(v0.x, nb); w0.y = __fdiv_rn(v0.y, nb);
        w0.z = __fdiv_rn(v0.z, nb); w0.w = __fdiv_rn(v0.w, nb);
        w1.x = __fdiv_rn(v1.x, nb); w1.y = __fdiv_rn(v1.y, nb);
        w1.z = __fdiv_rn(v1.z, nb); w1.w = __fdiv_rn(v1.w, nb);
        dst[lane] = w0; dst[lane + 32] = w1;
        if (lane == 0) g_rib[row] = __fdiv_rn(1.0f, nb);
    }
}

// ============ K1: sim GEMM — unchanged (serial, streaming stores) ============
#define BM 128
#define BN 128
#define BK 16

__global__ __launch_bounds__(256, 2) void gemm_sim_kernel(
    const int* __restrict__ ay, const int* __restrict__ by) {
    __shared__ float As[2][BK][BM];
    __shared__ float Bs[2][BK][BN];
    const float* __restrict__ A = g_An;
    const float* __restrict__ B = g_Bn;

    const int tid = threadIdx.x;
    const int tx = tid & 15, ty = tid >> 4;
    const int tx4 = tx * 4, ty4 = ty * 4;
    const int row0 = blockIdx.y * BM;
    const int col0 = blockIdx.x * BN;

    const int f0 = tid * 2;
    const int r0 = f0 >> 2,        c0 = (f0 & 3) * 4;
    const int r1 = (f0 + 1) >> 2,  c1 = ((f0 + 1) & 3) * 4;

    u64 acc2[8][4];
#pragma unroll
    for (int i = 0; i < 8; ++i)
#pragma unroll
        for (int jp = 0; jp < 4; ++jp) acc2[i][jp] = pack2(0.f, 0.f);

    float4 ra0, ra1, rb0, rb1;
    ra0 = *(const float4*)(A + (size_t)(row0 + r0) * DD + c0);
    ra1 = *(const float4*)(A + (size_t)(row0 + r1) * DD + c1);
    rb0 = *(const float4*)(B + (size_t)(col0 + r0) * DD + c0);
    rb1 = *(const float4*)(B + (size_t)(col0 + r1) * DD + c1);
    As[0][c0 + 0][r0] = ra0.x; As[0][c0 + 1][r0] = ra0.y; As[0][c0 + 2][r0] = ra0.z; As[0][c0 + 3][r0] = ra0.w;
    As[0][c1 + 0][r1] = ra1.x; As[0][c1 + 1][r1] = ra1.y; As[0][c1 + 2][r1] = ra1.z; As[0][c1 + 3][r1] = ra1.w;
    Bs[0][c0 + 0][r0] = rb0.x; Bs[0][c0 + 1][r0] = rb0.y; Bs[0][c0 + 2][r0] = rb0.z; Bs[0][c0 + 3][r0] = rb0.w;
    Bs[0][c1 + 0][r1] = rb1.x; Bs[0][c1 + 1][r1] = rb1.y; Bs[0][c1 + 2][r1] = rb1.z; Bs[0][c1 + 3][r1] = rb1.w;
    __syncthreads();

    const int NT = DD / BK;  // 16
    for (int t = 0; t < NT; ++t) {
        const int p = t & 1;
        const int kt = (t + 1) * BK;
        if (t + 1 < NT) {
            ra0 = *(const float4*)(A + (size_t)(row0 + r0) * DD + kt + c0);
            ra1 = *(const float4*)(A + (size_t)(row0 + r1) * DD + kt + c1);
            rb0 = *(const float4*)(B + (size_t)(col0 + r0) * DD + kt + c0);
            rb1 = *(const float4*)(B + (size_t)(col0 + r1) * DD + kt + c1);
        }
#pragma unroll
        for (int k = 0; k < BK; ++k) {
            float4 a0 = *(const float4*)&As[p][k][ty4];
            float4 a1 = *(const float4*)&As[p][k][64 + ty4];
            ulonglong2 bq0 = *(const ulonglong2*)&Bs[p][k][tx4];
            ulonglong2 bq1 = *(const ulonglong2*)&Bs[p][k][64 + tx4];
            u64 bp[4] = {bq0.x, bq0.y, bq1.x, bq1.y};
            float av[8] = {a0.x, a0.y, a0.z, a0.w, a1.x, a1.y, a1.z, a1.w};
#pragma unroll
            for (int i = 0; i < 8; ++i) {
                u64 ad = pack2(av[i], av[i]);
#pragma unroll
                for (int jp = 0; jp < 4; ++jp)
                    acc2[i][jp] = ffma2(ad, bp[jp], acc2[i][jp]);
            }
        }
        if (t + 1 < NT) {
            const int q = p ^ 1;
            As[q][c0 + 0][r0] = ra0.x; As[q][c0 + 1][r0] = ra0.y; As[q][c0 + 2][r0] = ra0.z; As[q][c0 + 3][r0] = ra0.w;
            As[q][c1 + 0][r1] = ra1.x; As[q][c1 + 1][r1] = ra1.y; As[q][c1 + 2][r1] = ra1.z; As[q][c1 + 3][r1] = ra1.w;
            Bs[q][c0 + 0][r0] = rb0.x; Bs[q][c0 + 1][r0] = rb0.y; Bs[q][c0 + 2][r0] = rb0.z; Bs[q][c0 + 3][r0] = rb0.w;
            Bs[q][c1 + 0][r1] = rb1.x; Bs[q][c1 + 1][r1] = rb1.y; Bs[q][c1 + 2][r1] = rb1.z; Bs[q][c1 + 3][r1] = rb1.w;
            __syncthreads();
        }
    }

    int rw[8], cl[8];
#pragma unroll
    for (int i = 0; i < 8; ++i) rw[i] = row0 + ((i < 4) ? (ty4 + i) : (64 + ty4 + i - 4));
#pragma unroll
    for (int j = 0; j < 8; ++j) cl[j] = col0 + ((j < 4) ? (tx4 + j) : (64 + tx4 + j - 4));

    float ria[8], rib_[8];
    int la[8], lb[8];
#pragma unroll
    for (int i = 0; i < 8; ++i) { ria[i] = g_ria[rw[i]]; la[i] = ay[rw[i]]; }
#pragma unroll
    for (int j = 0; j < 8; ++j) { rib_[j] = g_rib[cl[j]]; lb[j] = by[cl[j]]; }

#pragma unroll
    for (int i = 0; i < 8; ++i) {
        float accf[8];
#pragma unroll
        for (int jp = 0; jp < 4; ++jp) unpack2(acc2[i][jp], accf[2 * jp], accf[2 * jp + 1]);
        float v[8];
#pragma unroll
        for (int j = 0; j < 8; ++j) {
            float sv = (la[i] == lb[j]) ? fmaf(ria[i], rib_[j], accf[j]) : accf[j];
            if (rw[i] == cl[j]) sv = 0.0f;
            v[j] = sv;
        }
        __stcs((float4*)&g_S[(size_t)rw[i] * NN + (col0 + tx4)],
               make_float4(v[0], v[1], v[2], v[3]));
        __stcs((float4*)&g_S[(size_t)rw[i] * NN + (col0 + 64 + tx4)],
               make_float4(v[4], v[5], v[6], v[7]));
    }
}

// ======== K2: R12 structure, histogram deleted (b1 from row max), pass-C compaction ========
__device__ __forceinline__ unsigned fkey(float v) {
    unsigned b = __float_as_uint(v);
    return (b & 0x80000000u) ? ~b : (b | 0x80000000u);
}

__global__ __launch_bounds__(256) void topk_out_kernel(
    const float* __restrict__ Eb,
    const int* __restrict__ ay, const int* __restrict__ by,
    float* __restrict__ out) {
    __shared__ float rowv[NN];                 // 32 KB
    __shared__ unsigned hist[256];             // radix histograms
    __shared__ float redf[8];
    __shared__ unsigned short cmpi[CMPCAP];    // 2.75 KB
    __shared__ float cv[CAND];
    __shared__ int   ci[CAND];
    __shared__ unsigned ckey[CAND];
    __shared__ float cgam[CAND];
    __shared__ float topg[KK];
    __shared__ int   topi[KK];
    __shared__ float buv[KK];
    __shared__ unsigned cntC, cntG, cntE;
    __shared__ float sh_max, sh_den;
    __shared__ int sh_sel, sh_above;

    const int tid = threadIdx.x;
    const int lane = tid & 31, warp = tid >> 5;
    const int row = blockIdx.x;
    const float* Srow = g_S + (size_t)row * NN;

    // ---- pass A: load (streaming) + fused row max ----
    float m = -1e30f;
    for (int i = tid; i < NN / 4; i += 256) {
        float4 v = __ldcs((const float4*)Srow + i);
        ((float4*)rowv)[i] = v;
        m = fmaxf(m, fmaxf(fmaxf(v.x, v.y), fmaxf(v.z, v.w)));
    }
#pragma unroll
    for (int o = 16; o; o >>= 1) m = fmaxf(m, __shfl_xor_sync(0xffffffffu, m, o));
    if (lane == 0) redf[warp] = m;
    __syncthreads();
    if (tid == 0) {
        float mm = redf[0];
#pragma unroll
        for (int w = 1; w < 8; ++w) mm = fmaxf(mm, redf[w]);
        sh_max = mm;
        // conservative MSB cut, free from the max: one exponent-byte below the
        // row max's byte. Any b1 whose bucket-set holds >= CAND elements gives a
        // superset of the true top-CAND -> identical pivot. Fallback-guarded.
        sh_sel = (int)((fkey(mm) >> 24) - 1u);
        cntC = 0;
    }
    __syncthreads();
    m = sh_max;
    const unsigned b1 = (unsigned)sh_sel;

    // ---- pass B: PURE pexp-sum (EXACT same loop order => same den bits) ----
    float s = 0.f;
    for (int i = tid; i < NN; i += 256) s += pexp_eigen(__fadd_rn(rowv[i], -m));
#pragma unroll
    for (int o = 16; o; o >>= 1) s += __shfl_xor_sync(0xffffffffu, s, o);
    if (lane == 0) redf[warp] = s;
    __syncthreads();
    if (tid == 0) {
        float ss = 0.f;
#pragma unroll
        for (int w = 0; w < 8; ++w) ss += redf[w];
        sh_den = ss;
    }
    __syncthreads();
    const float den = sh_den;

    // ---- pass C: compact indices with MSB >= b1 (LDS-bound, atomics off hot path) ----
    for (int i = tid; i < NN; i += 256) {
        if ((fkey(rowv[i]) >> 24) >= b1) {
            unsigned p = atomicAdd(&cntC, 1u);
            if (p < CMPCAP) cmpi[p] = (unsigned short)i;
        }
    }
    __syncthreads();
    // fallback: cut too tight (< CAND) or overflowed capacity -> full-row radix
    const bool compact = (cntC >= CAND) && (cntC <= CMPCAP);
    const int cnt = compact ? (int)cntC : NN;

    // ---- 4-level radix select (compacted set, or full row in fallback) ----
    unsigned prefix = 0;
    int remaining = CAND;
    int prefbits = 0;
    for (int shift = 24; shift >= 0; shift -= 8) {
        hist[tid] = 0;
        __syncthreads();
        for (int i = tid; i < cnt; i += 256) {
            unsigned u = fkey(rowv[compact ? (int)cmpi[i] : i]);
            bool ok = (prefbits == 0) || ((u >> (shift + 8)) == prefix);
            if (ok) atomicAdd(&hist[(u >> shift) & 255u], 1u);
        }
        __syncthreads();
        if (tid == 0) {
            int cum = 0, b = 255;
            for (; b > 0; --b) {
                int c = (int)hist[b];
                if (cum + c >= remaining) break;
                cum += c;
            }
            sh_sel = b;
            sh_above = cum;
        }
        __syncthreads();
        prefix = (prefix << 8) | (unsigned)sh_sel;
        remaining -= sh_above;
        prefbits += 8;
    }
    const unsigned pivot = prefix;
    const int G = CAND - remaining;

    if (tid == 0) { cntG = 0; cntE = 0; }
    __syncthreads();
    for (int i = tid; i < cnt; i += 256) {
        int idx = compact ? (int)cmpi[i] : i;
        float v = rowv[idx];
        unsigned u = fkey(v);
        if (u > pivot) {
            unsigned p = atomicAdd(&cntG, 1u);
            cv[p] = v; ci[p] = idx;
        } else if (u == pivot) {
            unsigned p = atomicAdd(&cntE, 1u);
            if ((int)p < remaining) { cv[G + p] = v; ci[G + p] = idx; }
        }
    }
    __syncthreads();

    // ---- gamma keys for candidates (unchanged arithmetic) ----
    if (tid < CAND) {
        float num = pexp_eigen(__fadd_rn(cv[tid], -m));
        float gam = __fdiv_rn(num, den);
        cgam[tid] = gam;
        ckey[tid] = fkey(gam);
    }
    __syncthreads();

    // exact top-KK by (gamma desc, index asc)
    if (tid < CAND) {
        unsigned kt = ckey[tid]; int jt = ci[tid];
        int rank = 0;
#pragma unroll 4
        for (int c = 0; c < CAND; ++c) {
            unsigned kc = ckey[c];
            if (kc > kt || (kc == kt && ci[c] < jt)) rank++;
        }
        if (rank < KK) { topg[rank] = cgam[tid]; topi[rank] = jt; }
    }
    __syncthreads();

    // b_uv = softmax(scalar * gamma) over K
    if (tid < KK) {
        int j = topi[tid];
        float sc = (ay[row] == by[j]) ? 1.0f : 0.96875f;
        float w = __fmul_rn(sc, topg[tid]);
        float wm = w;
#pragma unroll
        for (int o = 16; o; o >>= 1) wm = fmaxf(wm, __shfl_xor_sync(0xffffffffu, wm, o));
        float e = pexp_eigen(__fadd_rn(w, -wm));
        float es = e;
#pragma unroll
        for (int o = 16; o; o >>= 1) es += __shfl_xor_sync(0xffffffffu, es, o);
        buv[tid] = __fdiv_rn(e, es);
    }
    __syncthreads();

    float accv = 0.f;
#pragma unroll
    for (int k = 0; k < KK; ++k)
        accv += buv[k] * Eb[(size_t)topi[k] * DD + tid];
    out[(size_t)row * DD + tid] = accv;
}

// =========================== launch (serial) ===========================
extern "C" void kernel_launch(void* const* d_in, const int* in_sizes, int n_in,
                              void* d_out, int out_size) {
    const float* Ea = (const float*)d_in[0];
    const float* Eb = (const float*)d_in[1];
    const int* ay = (const int*)d_in[2];
    const int* by = (const int*)d_in[3];
    float* out = (float*)d_out;

    normalize_kernel<<<NN / 8, 256>>>(Ea, Eb);
    gemm_sim_kernel<<<dim3(NN / BN, NN / BM), 256>>>(ay, by);
    topk_out_kernel<<<NN, 256>>>(Eb, ay, by, out);
}

// round 15
// speedup vs baseline: 1.1328x; 1.1328x over previous
#include <cuda_runtime.h>
#include <cstdint>

#define NN 8192
#define DD 256
#define KK 32
#define CAND 48
#define CMPCAP 1408

typedef unsigned long long u64;

// ---- scratch (no cudaMalloc allowed) ----
__device__ float g_S[(size_t)NN * (size_t)NN];   // 256 MB sim matrix
__device__ float g_An[(size_t)NN * DD];          // fp32-normalized A (ref rounding)
__device__ float g_Bn[(size_t)NN * DD];          // fp32-normalized B
__device__ float g_ria[NN];                      // fl(1/na) -- normalized one-hot element
__device__ float g_rib[NN];

// ===== packed dual-fp32 FMA =====
__device__ __forceinline__ u64 pack2(float lo, float hi) {
    u64 r; asm("mov.b64 %0, {%1, %2};" : "=l"(r) : "f"(lo), "f"(hi)); return r;
}
__device__ __forceinline__ void unpack2(u64 v, float& lo, float& hi) {
    asm("mov.b64 {%0, %1}, %2;" : "=f"(lo), "=f"(hi) : "l"(v));
}
__device__ __forceinline__ u64 ffma2(u64 a, u64 b, u64 c) {
    u64 d; asm("fma.rn.f32x2 %0, %1, %2, %3;" : "=l"(d) : "l"(a), "l"(b), "l"(c)); return d;
}

// ===== Eigen pexp, range-specialized for x in [-2.3, 0] =====
// Verified bit-identical (R11/R12): clamp, lo-branch and final fmax are
// identities on this domain; single power-of-2 scale suffices.
__device__ __forceinline__ float pexp_eigen(float x) {
    const float cst_LOG2EF = 1.44269504088896341f;
    const float p0 = 1.9875691500E-4f, p1 = 1.3981999507E-3f, p2 = 8.3334519073E-3f;
    const float p3 = 4.1665795894E-2f, p4 = 1.6666665459E-1f, p5 = 5.0000001201E-1f;
    float m = floorf(__fmaf_rn(x, cst_LOG2EF, 0.5f));
    const float cst_nln2 = -0.6931471805599453f;
    float r  = __fmaf_rn(m, cst_nln2, x);
    float r2 = __fmul_rn(r, r);
    float r3 = __fmul_rn(r2, r);
    float y  = __fmaf_rn(p0, r, p1);
    float y1 = __fmaf_rn(p3, r, p4);
    float y2 = __fadd_rn(r, 1.0f);
    y  = __fmaf_rn(y, r, p2);
    y1 = __fmaf_rn(y1, r, p5);
    y  = __fmaf_rn(y, r3, y1);
    y  = __fmaf_rn(y, r2, y2);
    float f1 = __uint_as_float((unsigned)(127 + (int)m) << 23);
    return __fmul_rn(y, f1);
}

// =========== K0: fp32 normalization like the reference (UNCHANGED bits) ===========
__global__ __launch_bounds__(256) void normalize_kernel(const float* __restrict__ A,
                                                        const float* __restrict__ B) {
    int warp = threadIdx.x >> 5, lane = threadIdx.x & 31;
    int row = blockIdx.x * 8 + warp;
    if (row >= NN) return;

    {
        const float4* ar = (const float4*)(A + (size_t)row * DD);
        float4 v0 = ar[lane], v1 = ar[lane + 32];
        double s = (double)v0.x * v0.x + (double)v0.y * v0.y +
                   (double)v0.z * v0.z + (double)v0.w * v0.w +
                   (double)v1.x * v1.x + (double)v1.y * v1.y +
                   (double)v1.z * v1.z + (double)v1.w * v1.w;
#pragma unroll
        for (int o = 16; o; o >>= 1) s += __shfl_xor_sync(0xffffffffu, s, o);
        float na = __fsqrt_rn((float)(s + 1.0));
        float4* dst = (float4*)(g_An + (size_t)row * DD);
        float4 w0, w1;
        w0.x = __fdiv_rn(v0.x, na); w0.y = __fdiv_rn(v0.y, na);
        w0.z = __fdiv_rn(v0.z, na); w0.w = __fdiv_rn(v0.w, na);
        w1.x = __fdiv_rn(v1.x, na); w1.y = __fdiv_rn(v1.y, na);
        w1.z = __fdiv_rn(v1.z, na); w1.w = __fdiv_rn(v1.w, na);
        dst[lane] = w0; dst[lane + 32] = w1;
        if (lane == 0) g_ria[row] = __fdiv_rn(1.0f, na);
    }
    {
        const float4* br = (const float4*)(B + (size_t)row * DD);
        float4 v0 = br[lane], v1 = br[lane + 32];
        double s = (double)v0.x * v0.x + (double)v0.y * v0.y +
                   (double)v0.z * v0.z + (double)v0.w * v0.w +
                   (double)v1.x * v1.x + (double)v1.y * v1.y +
                   (double)v1.z * v1.z + (double)v1.w * v1.w;
#pragma unroll
        for (int o = 16; o; o >>= 1) s += __shfl_xor_sync(0xffffffffu, s, o);
        float nb = __fsqrt_rn((float)(s + 1.0));
        float4* dst = (float4*)(g_Bn + (size_t)row * DD);
        float4 w0, w1;
        w0.x = __fdiv_rn(v0.x, nb); w0.y = __fdiv_rn(v0.y, nb);
        w0.z = __fdiv_rn(v0.z, nb); w0.w = __fdiv_rn(v0.w, nb);
        w1.x = __fdiv_rn(v1.x, nb); w1.y = __fdiv_rn(v1.y, nb);
        w1.z = __fdiv_rn(v1.z, nb); w1.w = __fdiv_rn(v1.w, nb);
        dst[lane] = w0; dst[lane + 32] = w1;
        if (lane == 0) g_rib[row] = __fdiv_rn(1.0f, nb);
    }
}

// ============ K1: sim GEMM — FFMA2, double-buffered, streaming stores ============
#define BM 128
#define BN 128
#define BK 16

__global__ __launch_bounds__(256, 2) void gemm_sim_kernel(
    const int* __restrict__ ay, const int* __restrict__ by) {
    __shared__ float As[2][BK][BM];
    __shared__ float Bs[2][BK][BN];
    const float* __restrict__ A = g_An;
    const float* __restrict__ B = g_Bn;

    const int tid = threadIdx.x;
    const int tx = tid & 15, ty = tid >> 4;
    const int tx4 = tx * 4, ty4 = ty * 4;
    const int row0 = blockIdx.y * BM;
    const int col0 = blockIdx.x * BN;

    const int f0 = tid * 2;
    const int r0 = f0 >> 2,        c0 = (f0 & 3) * 4;
    const int r1 = (f0 + 1) >> 2,  c1 = ((f0 + 1) & 3) * 4;

    u64 acc2[8][4];
#pragma unroll
    for (int i = 0; i < 8; ++i)
#pragma unroll
        for (int jp = 0; jp < 4; ++jp) acc2[i][jp] = pack2(0.f, 0.f);

    float4 ra0, ra1, rb0, rb1;
    ra0 = *(const float4*)(A + (size_t)(row0 + r0) * DD + c0);
    ra1 = *(const float4*)(A + (size_t)(row0 + r1) * DD + c1);
    rb0 = *(const float4*)(B + (size_t)(col0 + r0) * DD + c0);
    rb1 = *(const float4*)(B + (size_t)(col0 + r1) * DD + c1);
    As[0][c0 + 0][r0] = ra0.x; As[0][c0 + 1][r0] = ra0.y; As[0][c0 + 2][r0] = ra0.z; As[0][c0 + 3][r0] = ra0.w;
    As[0][c1 + 0][r1] = ra1.x; As[0][c1 + 1][r1] = ra1.y; As[0][c1 + 2][r1] = ra1.z; As[0][c1 + 3][r1] = ra1.w;
    Bs[0][c0 + 0][r0] = rb0.x; Bs[0][c0 + 1][r0] = rb0.y; Bs[0][c0 + 2][r0] = rb0.z; Bs[0][c0 + 3][r0] = rb0.w;
    Bs[0][c1 + 0][r1] = rb1.x; Bs[0][c1 + 1][r1] = rb1.y; Bs[0][c1 + 2][r1] = rb1.z; Bs[0][c1 + 3][r1] = rb1.w;
    __syncthreads();

    const int NT = DD / BK;  // 16
    for (int t = 0; t < NT; ++t) {
        const int p = t & 1;
        const int kt = (t + 1) * BK;
        if (t + 1 < NT) {
            ra0 = *(const float4*)(A + (size_t)(row0 + r0) * DD + kt + c0);
            ra1 = *(const float4*)(A + (size_t)(row0 + r1) * DD + kt + c1);
            rb0 = *(const float4*)(B + (size_t)(col0 + r0) * DD + kt + c0);
            rb1 = *(const float4*)(B + (size_t)(col0 + r1) * DD + kt + c1);
        }
#pragma unroll
        for (int k = 0; k < BK; ++k) {
            float4 a0 = *(const float4*)&As[p][k][ty4];
            float4 a1 = *(const float4*)&As[p][k][64 + ty4];
            ulonglong2 bq0 = *(const ulonglong2*)&Bs[p][k][tx4];
            ulonglong2 bq1 = *(const ulonglong2*)&Bs[p][k][64 + tx4];
            u64 bp[4] = {bq0.x, bq0.y, bq1.x, bq1.y};
            float av[8] = {a0.x, a0.y, a0.z, a0.w, a1.x, a1.y, a1.z, a1.w};
#pragma unroll
            for (int i = 0; i < 8; ++i) {
                u64 ad = pack2(av[i], av[i]);
#pragma unroll
                for (int jp = 0; jp < 4; ++jp)
                    acc2[i][jp] = ffma2(ad, bp[jp], acc2[i][jp]);
            }
        }
        if (t + 1 < NT) {
            const int q = p ^ 1;
            As[q][c0 + 0][r0] = ra0.x; As[q][c0 + 1][r0] = ra0.y; As[q][c0 + 2][r0] = ra0.z; As[q][c0 + 3][r0] = ra0.w;
            As[q][c1 + 0][r1] = ra1.x; As[q][c1 + 1][r1] = ra1.y; As[q][c1 + 2][r1] = ra1.z; As[q][c1 + 3][r1] = ra1.w;
            Bs[q][c0 + 0][r0] = rb0.x; Bs[q][c0 + 1][r0] = rb0.y; Bs[q][c0 + 2][r0] = rb0.z; Bs[q][c0 + 3][r0] = rb0.w;
            Bs[q][c1 + 0][r1] = rb1.x; Bs[q][c1 + 1][r1] = rb1.y; Bs[q][c1 + 2][r1] = rb1.z; Bs[q][c1 + 3][r1] = rb1.w;
            __syncthreads();
        }
    }

    int rw[8], cl[8];
#pragma unroll
    for (int i = 0; i < 8; ++i) rw[i] = row0 + ((i < 4) ? (ty4 + i) : (64 + ty4 + i - 4));
#pragma unroll
    for (int j = 0; j < 8; ++j) cl[j] = col0 + ((j < 4) ? (tx4 + j) : (64 + tx4 + j - 4));

    float ria[8], rib_[8];
    int la[8], lb[8];
#pragma unroll
    for (int i = 0; i < 8; ++i) { ria[i] = g_ria[rw[i]]; la[i] = ay[rw[i]]; }
#pragma unroll
    for (int j = 0; j < 8; ++j) { rib_[j] = g_rib[cl[j]]; lb[j] = by[cl[j]]; }

#pragma unroll
    for (int i = 0; i < 8; ++i) {
        float accf[8];
#pragma unroll
        for (int jp = 0; jp < 4; ++jp) unpack2(acc2[i][jp], accf[2 * jp], accf[2 * jp + 1]);
        float v[8];
#pragma unroll
        for (int j = 0; j < 8; ++j) {
            float sv = (la[i] == lb[j]) ? fmaf(ria[i], rib_[j], accf[j]) : accf[j];
            if (rw[i] == cl[j]) sv = 0.0f;
            v[j] = sv;
        }
        __stcs((float4*)&g_S[(size_t)rw[i] * NN + (col0 + tx4)],
               make_float4(v[0], v[1], v[2], v[3]));
        __stcs((float4*)&g_S[(size_t)rw[i] * NN + (col0 + 64 + tx4)],
               make_float4(v[4], v[5], v[6], v[7]));
    }
}

// ======== K2: R12 — hist in pass B, specialized pexp, compacted radix ========
__device__ __forceinline__ unsigned fkey(float v) {
    unsigned b = __float_as_uint(v);
    return (b & 0x80000000u) ? ~b : (b | 0x80000000u);
}

__global__ __launch_bounds__(256) void topk_out_kernel(
    const float* __restrict__ Eb,
    const int* __restrict__ ay, const int* __restrict__ by,
    float* __restrict__ out) {
    __shared__ float rowv[NN];                 // 32 KB
    __shared__ unsigned hist[256];             // 1 KB
    __shared__ float redf[8];
    __shared__ unsigned short cmpi[CMPCAP];    // 2.75 KB
    __shared__ float cv[CAND];
    __shared__ int   ci[CAND];
    __shared__ unsigned ckey[CAND];
    __shared__ float cgam[CAND];
    __shared__ float topg[KK];
    __shared__ int   topi[KK];
    __shared__ float buv[KK];
    __shared__ unsigned cntC, cntG, cntE;
    __shared__ float sh_max, sh_den;
    __shared__ int sh_sel, sh_above, sh_compact;

    const int tid = threadIdx.x;
    const int lane = tid & 31, warp = tid >> 5;
    const int row = blockIdx.x;
    const float* Srow = g_S + (size_t)row * NN;

    // ---- pass A: load (streaming) + fused row max ----
    float m = -1e30f;
    for (int i = tid; i < NN / 4; i += 256) {
        float4 v = __ldcs((const float4*)Srow + i);
        ((float4*)rowv)[i] = v;
        m = fmaxf(m, fmaxf(fmaxf(v.x, v.y), fmaxf(v.z, v.w)));
    }
#pragma unroll
    for (int o = 16; o; o >>= 1) m = fmaxf(m, __shfl_xor_sync(0xffffffffu, m, o));
    if (lane == 0) redf[warp] = m;
    hist[tid] = 0;                 // init MSB histogram for pass B
    __syncthreads();
    if (tid == 0) {
        float mm = redf[0];
#pragma unroll
        for (int w = 1; w < 8; ++w) mm = fmaxf(mm, redf[w]);
        sh_max = mm;
    }
    __syncthreads();
    m = sh_max;

    // ---- pass B: pexp-sum (EXACT same loop order) + MSB-byte histogram ----
    float s = 0.f;
    for (int i = tid; i < NN; i += 256) {
        float v = rowv[i];
        unsigned b = fkey(v) >> 24;
        unsigned mk = __match_any_sync(0xffffffffu, b);
        if ((int)(__ffs(mk) - 1) == lane) atomicAdd(&hist[b], (unsigned)__popc(mk));
        s += pexp_eigen(__fadd_rn(v, -m));
    }
#pragma unroll
    for (int o = 16; o; o >>= 1) s += __shfl_xor_sync(0xffffffffu, s, o);
    if (lane == 0) redf[warp] = s;
    __syncthreads();
    if (tid == 0) {
        float ss = 0.f;
#pragma unroll
        for (int w = 0; w < 8; ++w) ss += redf[w];
        sh_den = ss;
        // MSB cut byte b1: smallest byte with count(>= b1) >= CAND
        int cum = 0, b = 255;
        for (; b > 0; --b) {
            int c = (int)hist[b];
            if (cum + c >= CAND) break;
            cum += c;
        }
        sh_sel = b;
        sh_compact = ((cum + (int)hist[b]) <= CMPCAP) ? 1 : 0;  // overflow -> full mode
        cntC = 0;
    }
    __syncthreads();
    const float den = sh_den;
    const unsigned b1 = (unsigned)sh_sel;
    const bool compact = (sh_compact != 0);

    // ---- pass C: compact indices with MSB >= b1 (skipped in fallback) ----
    if (compact) {
        for (int i = tid; i < NN; i += 256) {
            if ((fkey(rowv[i]) >> 24) >= b1) {
                unsigned p = atomicAdd(&cntC, 1u);
                cmpi[p] = (unsigned short)i;
            }
        }
    }
    __syncthreads();
    const int cnt = compact ? (int)cntC : NN;

    // ---- 4-level radix select (compacted set, or full row in fallback) ----
    unsigned prefix = 0;
    int remaining = CAND;
    int prefbits = 0;
    for (int shift = 24; shift >= 0; shift -= 8) {
        hist[tid] = 0;
        __syncthreads();
        for (int i = tid; i < cnt; i += 256) {
            unsigned u = fkey(rowv[compact ? (int)cmpi[i] : i]);
            bool ok = (prefbits == 0) || ((u >> (shift + 8)) == prefix);
            if (ok) atomicAdd(&hist[(u >> shift) & 255u], 1u);
        }
        __syncthreads();
        if (tid == 0) {
            int cum = 0, b = 255;
            for (; b > 0; --b) {
                int c = (int)hist[b];
                if (cum + c >= remaining) break;
                cum += c;
            }
            sh_sel = b;
            sh_above = cum;
        }
        __syncthreads();
        prefix = (prefix << 8) | (unsigned)sh_sel;
        remaining -= sh_above;
        prefbits += 8;
    }
    const unsigned pivot = prefix;
    const int G = CAND - remaining;

    if (tid == 0) { cntG = 0; cntE = 0; }
    __syncthreads();
    for (int i = tid; i < cnt; i += 256) {
        int idx = compact ? (int)cmpi[i] : i;
        float v = rowv[idx];
        unsigned u = fkey(v);
        if (u > pivot) {
            unsigned p = atomicAdd(&cntG, 1u);
            cv[p] = v; ci[p] = idx;
        } else if (u == pivot) {
            unsigned p = atomicAdd(&cntE, 1u);
            if ((int)p < remaining) { cv[G + p] = v; ci[G + p] = idx; }
        }
    }
    __syncthreads();

    // ---- gamma keys for candidates (unchanged arithmetic) ----
    if (tid < CAND) {
        float num = pexp_eigen(__fadd_rn(cv[tid], -m));
        float gam = __fdiv_rn(num, den);
        cgam[tid] = gam;
        ckey[tid] = fkey(gam);
    }
    __syncthreads();

    // exact top-KK by (gamma desc, index asc)
    if (tid < CAND) {
        unsigned kt = ckey[tid]; int jt = ci[tid];
        int rank = 0;
#pragma unroll 4
        for (int c = 0; c < CAND; ++c) {
            unsigned kc = ckey[c];
            if (kc > kt || (kc == kt && ci[c] < jt)) rank++;
        }
        if (rank < KK) { topg[rank] = cgam[tid]; topi[rank] = jt; }
    }
    __syncthreads();

    // b_uv = softmax(scalar * gamma) over K
    if (tid < KK) {
        int j = topi[tid];
        float sc = (ay[row] == by[j]) ? 1.0f : 0.96875f;
        float w = __fmul_rn(sc, topg[tid]);
        float wm = w;
#pragma unroll
        for (int o = 16; o; o >>= 1) wm = fmaxf(wm, __shfl_xor_sync(0xffffffffu, wm, o));
        float e = pexp_eigen(__fadd_rn(w, -wm));
        float es = e;
#pragma unroll
        for (int o = 16; o; o >>= 1) es += __shfl_xor_sync(0xffffffffu, es, o);
        buv[tid] = __fdiv_rn(e, es);
    }
    __syncthreads();

    float accv = 0.f;
#pragma unroll
    for (int k = 0; k < KK; ++k)
        accv += buv[k] * Eb[(size_t)topi[k] * DD + tid];
    out[(size_t)row * DD + tid] = accv;
}

// =========================== launch (serial) ===========================
extern "C" void kernel_launch(void* const* d_in, const int* in_sizes, int n_in,
                              void* d_out, int out_size) {
    const float* Ea = (const float*)d_in[0];
    const float* Eb = (const float*)d_in[1];
    const int* ay = (const int*)d_in[2];
    const int* by = (const int*)d_in[3];
    float* out = (float*)d_out;

    normalize_kernel<<<NN / 8, 256>>>(Ea, Eb);
    gemm_sim_kernel<<<dim3(NN / BN, NN / BM), 256>>>(ay, by);
    topk_out_kernel<<<NN, 256>>>(Eb, ay, by, out);
}